// round 11
// baseline (speedup 1.0000x reference)
#include <cuda_runtime.h>
#include <cuda_fp16.h>
#include <cstdint>

// Problem constants (fixed-shape problem: H=8, MH=8, N_NODES=500000)
#define H_DIM 8
#define MH_DIM 8
#define FEAT 64              // H*MH per sign
#define REC 128              // 2 signs * FEAT values per node record
#define MAX_NODES 500000
#define TILE_N 256           // nodes per transpose tile
#define TPB_T 512            // threads per transpose block

// Node-major scratch in fp16: [node][sign][h][mh], 256B per node,
// deg-normalization folded in. uint4 type guarantees 16B alignment.
__device__ uint4 g_pk_raw[(size_t)MAX_NODES * REC / 8];

// ---- L2 eviction-priority helpers (cache_hint form) ----
__device__ __forceinline__ uint64_t mk_evict_last_policy() {
    uint64_t pol;
    asm("createpolicy.fractional.L2::evict_last.b64 %0, 1.0;" : "=l"(pol));
    return pol;
}
__device__ __forceinline__ void st_hint_v4(void* p, uint4 v, uint64_t pol) {
    asm volatile("st.global.L2::cache_hint.v4.b32 [%0], {%1,%2,%3,%4}, %5;"
                 :: "l"(p), "r"(v.x), "r"(v.y), "r"(v.z), "r"(v.w), "l"(pol));
}
__device__ __forceinline__ uint4 ld_hint_v4(const void* p, uint64_t pol) {
    uint4 r;
    asm volatile("ld.global.L2::cache_hint.v4.u32 {%0,%1,%2,%3}, [%4], %5;"
                 : "=r"(r.x), "=r"(r.y), "=r"(r.z), "=r"(r.w)
                 : "l"(p), "l"(pol));
    return r;
}

// Swizzled half2-unit index of (feat f, node-pair p) in the 128 x 128-unit
// fp16 tile (row = 128 half2 units = 512B). XOR keeps bit0 intact so phase-1
// 8B paired stores stay aligned; phase-2 reads hit 32 distinct banks/warp.
__device__ __forceinline__ int su(int f, int p) {
    return f * 128 + (p ^ (((f >> 3) << 1) & 31));
}

// ---------------------------------------------------------------------------
// Kernel 1: transpose [s][h][mh][N] -> [N][s][h][mh] fp16, folding
// 1/max(deg,1). Block: 512 threads, tile 256 nodes x 128 features.
// Phase 1: float4 phi loads (1KB contiguous per feat-row per block),
//          scale + convert to fp16 into swizzled smem.
// Phase 2: per (node-pair, chunk) task: 8 half2 smem reads -> 2 uint4 stores
//          (16 lanes cover one node's 256B record contiguously).
// ---------------------------------------------------------------------------
__global__ __launch_bounds__(TPB_T) void transpose_fold_kernel(
    const float* __restrict__ phi_pos,
    const float* __restrict__ phi_neg,
    const float* __restrict__ deg_pos,
    const float* __restrict__ deg_neg,
    int n_nodes)
{
    __shared__ __align__(16) __half2 tile[128 * 128];   // 64KB
    __shared__ float inv[2][TILE_N][H_DIM];             // 16KB

    const int k0 = blockIdx.x * TILE_N;
    const int t  = threadIdx.x;
    const uint64_t pol = mk_evict_last_policy();

    // ---- inv: 2 signs * 256 nodes * 8 heads; float4 per (sign, node, h-half)
    #pragma unroll
    for (int it = 0; it < 2; ++it) {
        int fi   = t + it * TPB_T;          // 0..1023 float4 tasks
        int s    = fi >> 9;
        int rem  = fi & 511;
        int node = rem >> 1;
        int hh   = rem & 1;                 // heads 0-3 or 4-7
        int k    = k0 + node;
        float4 d = make_float4(1.f, 1.f, 1.f, 1.f);
        if (k < n_nodes) {
            const float* dp = s ? deg_neg : deg_pos;
            d = __ldcs(reinterpret_cast<const float4*>(
                dp + (size_t)k * H_DIM + hh * 4));
        }
        float4 r;
        r.x = 1.0f / fmaxf(d.x, 1.0f);
        r.y = 1.0f / fmaxf(d.y, 1.0f);
        r.z = 1.0f / fmaxf(d.z, 1.0f);
        r.w = 1.0f / fmaxf(d.w, 1.0f);
        *reinterpret_cast<float4*>(&inv[s][node][hh * 4]) = r;
    }
    __syncthreads();

    // ---- phase 1: 128 feat-rows x 64 float4 groups (256 nodes) ----
    // n_nodes % 4 == 0 and k0 % 4 == 0 -> each float4 is fully in or out.
    #pragma unroll
    for (int it = 0; it < 16; ++it) {
        int l = t + it * TPB_T;             // 0..8191
        int r = l >> 6;                     // feat row 0..127
        int g = l & 63;                     // float4 group (4 nodes)
        int kb = k0 + 4 * g;
        if (kb + 4 <= n_nodes) {
            int s = r >> 6;
            int f = r & 63;
            int h = f >> 3;
            const float* src = s ? phi_neg : phi_pos;
            float4 v = __ldcs(reinterpret_cast<const float4*>(
                src + (size_t)f * n_nodes + kb));
            int n0 = 4 * g;
            __half2 h0 = __floats2half2_rn(v.x * inv[s][n0 + 0][h],
                                           v.y * inv[s][n0 + 1][h]);
            __half2 h1 = __floats2half2_rn(v.z * inv[s][n0 + 2][h],
                                           v.w * inv[s][n0 + 3][h]);
            int u = su(r, 2 * g);           // even -> 8B aligned pair
            *reinterpret_cast<__half2*>(&tile[u])     = h0;
            *reinterpret_cast<__half2*>(&tile[u + 1]) = h1;
        }
        // out-of-range: leave smem garbage; phase-2 store guard skips it
    }
    __syncthreads();

    // ---- phase 2: 128 node-pairs x 16 chunks = 2048 tasks ----
    #pragma unroll
    for (int it = 0; it < 4; ++it) {
        int task = t + it * TPB_T;          // 0..2047
        int p = task >> 4;                  // node pair
        int c = task & 15;                  // 16B chunk (feats 8c..8c+7)
        int ka = k0 + 2 * p;
        int kb = ka + 1;
        __half va[8], vb[8];
        #pragma unroll
        for (int j = 0; j < 8; ++j) {
            __half2 v = tile[su(8 * c + j, p)];
            va[j] = __low2half(v);
            vb[j] = __high2half(v);
        }
        __half2 pa[4], pb[4];
        #pragma unroll
        for (int j = 0; j < 4; ++j) {
            pa[j] = __halves2half2(va[2 * j], va[2 * j + 1]);
            pb[j] = __halves2half2(vb[2 * j], vb[2 * j + 1]);
        }
        uint4 ua, ub;
        __builtin_memcpy(&ua, pa, 16);
        __builtin_memcpy(&ub, pb, 16);
        if (ka < n_nodes)
            st_hint_v4(g_pk_raw + (size_t)ka * (REC / 8) + c, ua, pol);
        if (kb < n_nodes)
            st_hint_v4(g_pk_raw + (size_t)kb * (REC / 8) + c, ub, pol);
    }
}

// ---------------------------------------------------------------------------
// Kernel 2: gather + dot (R7-proven). 8 threads per query; thread j = head j.
// out layout: [pos: nq*8][neg: nq*8]
// ---------------------------------------------------------------------------
__global__ __launch_bounds__(256) void gather_dot_kernel(
    const float* __restrict__ q_phi,
    const int*   __restrict__ k_indices,
    float* __restrict__ out,
    int nq)
{
    int t = blockIdx.x * blockDim.x + threadIdx.x;
    int i = t >> 3;
    if (i >= nq) return;
    int h = t & 7;

    const uint64_t pol = mk_evict_last_policy();

    int k = __ldcs(k_indices + i);

    const float4* qp = reinterpret_cast<const float4*>(
        q_phi + (size_t)i * FEAT + h * MH_DIM);
    float4 q0 = __ldcs(qp);
    float4 q1 = __ldcs(qp + 1);

    const uint4* rec = g_pk_raw + (size_t)k * (REC / 8);
    uint4 pr = ld_hint_v4(rec + h, pol);
    uint4 nr = ld_hint_v4(rec + 8 + h, pol);

    const __half2* ph = reinterpret_cast<const __half2*>(&pr);
    const __half2* nh = reinterpret_cast<const __half2*>(&nr);

    float2 p0 = __half22float2(ph[0]);
    float2 p1 = __half22float2(ph[1]);
    float2 p2 = __half22float2(ph[2]);
    float2 p3 = __half22float2(ph[3]);
    float2 n0 = __half22float2(nh[0]);
    float2 n1 = __half22float2(nh[1]);
    float2 n2 = __half22float2(nh[2]);
    float2 n3 = __half22float2(nh[3]);

    float dp = q0.x * p0.x + q0.y * p0.y + q0.z * p1.x + q0.w * p1.y
             + q1.x * p2.x + q1.y * p2.y + q1.z * p3.x + q1.w * p3.y;
    float dn = q0.x * n0.x + q0.y * n0.y + q0.z * n1.x + q0.w * n1.y
             + q1.x * n2.x + q1.y * n2.y + q1.z * n3.x + q1.w * n3.y;

    __stcs(out + (size_t)i * H_DIM + h, dp);
    __stcs(out + (size_t)nq * H_DIM + (size_t)i * H_DIM + h, dn);
}

extern "C" void kernel_launch(void* const* d_in, const int* in_sizes, int n_in,
                              void* d_out, int out_size)
{
    const float* q_phi   = (const float*)d_in[0];
    const float* phi_pos = (const float*)d_in[1];
    const float* phi_neg = (const float*)d_in[2];
    const float* deg_pos = (const float*)d_in[3];
    const float* deg_neg = (const float*)d_in[4];
    const int*   k_idx   = (const int*)d_in[5];

    int nq      = in_sizes[5];                    // k_indices has N_Q elements
    int n_nodes = in_sizes[3] / H_DIM;            // deg_pos is [N][H]
    if (n_nodes > MAX_NODES) n_nodes = MAX_NODES;

    int tblocks = (n_nodes + TILE_N - 1) / TILE_N;
    transpose_fold_kernel<<<tblocks, TPB_T>>>(phi_pos, phi_neg, deg_pos,
                                              deg_neg, n_nodes);

    int total   = nq * H_DIM;
    int gblocks = (total + 255) / 256;
    gather_dot_kernel<<<gblocks, 256>>>(q_phi, k_idx, (float*)d_out, nq);
}

// round 12
// speedup vs baseline: 2.0235x; 2.0235x over previous
#include <cuda_runtime.h>
#include <cuda_fp16.h>
#include <cstdint>

// Problem constants (fixed-shape problem: H=8, MH=8, N_NODES=500000)
#define H_DIM 8
#define MH_DIM 8
#define FEAT 64              // H*MH per sign
#define REC 128              // 2 signs * FEAT values per node record
#define MAX_NODES 500000
#define TILE_N 64            // nodes per transpose tile

// Node-major scratch in fp16: [node][sign][h][mh], 256B per node,
// deg-normalization folded in. uint4 type guarantees 16B alignment.
__device__ uint4 g_pk_raw[(size_t)MAX_NODES * REC / 8];

// ---- L2 eviction-priority helpers (cache_hint form) ----
__device__ __forceinline__ uint64_t mk_evict_last_policy() {
    uint64_t pol;
    asm("createpolicy.fractional.L2::evict_last.b64 %0, 1.0;" : "=l"(pol));
    return pol;
}
__device__ __forceinline__ void st_hint_v4(void* p, uint4 v, uint64_t pol) {
    asm volatile("st.global.L2::cache_hint.v4.b32 [%0], {%1,%2,%3,%4}, %5;"
                 :: "l"(p), "r"(v.x), "r"(v.y), "r"(v.z), "r"(v.w), "l"(pol));
}
__device__ __forceinline__ uint4 ld_hint_v4(const void* p, uint64_t pol) {
    uint4 r;
    asm volatile("ld.global.L2::cache_hint.v4.u32 {%0,%1,%2,%3}, [%4], %5;"
                 : "=r"(r.x), "=r"(r.y), "=r"(r.z), "=r"(r.w)
                 : "l"(p), "l"(pol));
    return r;
}

// Swizzled byte offset of (feat f, node n) in the 128x64 float tile
// (row = 256B). Conflict-free phase-1 stores, <=2-way phase-2 reads.
__device__ __forceinline__ int sw_byte(int f, int n) {
    int off = f * 256 + n * 4;
    int x = ((off >> 7) ^ (off >> 11)) & 7;
    return off ^ (x << 4);
}

// ---------------------------------------------------------------------------
// Kernel 1: transpose [s][h][mh][N] -> [N][s][h][mh] fp16, folding
// 1/max(deg,1). Block: 256 threads, tile 64 nodes x 128 features.
// inv is stored TRANSPOSED as inv_t[s][h][node] so phase-1 reads the 4
// per-node scales as one contiguous float4 (<=2-way banked) instead of the
// R7 layout's 16-way single-bank conflict.
// ---------------------------------------------------------------------------
__global__ __launch_bounds__(256) void transpose_fold_kernel(
    const float* __restrict__ phi_pos,
    const float* __restrict__ phi_neg,
    const float* __restrict__ deg_pos,
    const float* __restrict__ deg_neg,
    int n_nodes)
{
    __shared__ __align__(16) char tile_raw[128 * 256];   // 32KB
    __shared__ __align__(16) float inv_t[2][H_DIM][TILE_N];  // 4KB, transposed

    const int k0 = blockIdx.x * TILE_N;
    const int t  = threadIdx.x;
    const uint64_t pol = mk_evict_last_policy();
    const bool full = (k0 + TILE_N <= n_nodes) && ((n_nodes & 3) == 0);

    // ---- inv table: 2*64*8 = 1024 values, deg read coalesced ----
    #pragma unroll
    for (int it = 0; it < 4; ++it) {
        int idx  = t + it * 256;            // s*512 + node*8 + h
        int s    = idx >> 9;
        int node = (idx >> 3) & 63;
        int h    = idx & 7;
        int k    = k0 + node;
        float d  = 1.0f;
        if (k < n_nodes) {
            const float* dp = s ? deg_neg : deg_pos;
            d = __ldcs(dp + (size_t)k * H_DIM + h);
        }
        inv_t[s][h][node] = 1.0f / fmaxf(d, 1.0f);
    }
    __syncthreads();   // inv_t ready before scaled loads

    // ---- phase 1: load 128 feat-rows x 64 nodes ----
    if (full) {
        #pragma unroll
        for (int it = 0; it < 8; ++it) {
            int l = t + it * 256;           // 0..2047
            int r = l >> 4;                 // feat row 0..127
            int g = l & 15;                 // float4 group (4 nodes)
            int s = r >> 6;
            int f = r & 63;
            int h = f >> 3;
            const float* src = s ? phi_neg : phi_pos;
            float4 v = __ldcs(reinterpret_cast<const float4*>(
                src + (size_t)f * n_nodes + k0 + 4 * g));
            float4 iv = *reinterpret_cast<const float4*>(&inv_t[s][h][4 * g]);
            v.x *= iv.x; v.y *= iv.y; v.z *= iv.z; v.w *= iv.w;
            *reinterpret_cast<float4*>(tile_raw + sw_byte(r, 4 * g)) = v;
        }
    } else {
        #pragma unroll 4
        for (int it = 0; it < 32; ++it) {
            int l  = t + it * 256;          // 128*64 = 8192 elements
            int r  = l >> 6;
            int kk = l & 63;
            int k  = k0 + kk;
            int s  = r >> 6;
            int f  = r & 63;
            int h  = f >> 3;
            float v = 0.0f;
            if (k < n_nodes) {
                const float* src = s ? phi_neg : phi_pos;
                v = __ldcs(src + (size_t)f * n_nodes + k) * inv_t[s][h][kk];
            }
            *reinterpret_cast<float*>(tile_raw + sw_byte(r, kk)) = v;
        }
    }
    __syncthreads();

    // ---- phase 2: 64 nodes x 16 chunks; chunk c = feats 8c..8c+7 ----
    // (inv already folded in phase 1: convert only)
    #pragma unroll
    for (int it = 0; it < 4; ++it) {
        int l    = t + it * 256;            // 0..1023
        int node = l >> 4;
        int c    = l & 15;
        int k    = k0 + node;
        if (k < n_nodes) {
            __half2 hh[4];
            #pragma unroll
            for (int j = 0; j < 8; j += 2) {
                float a = *reinterpret_cast<const float*>(
                              tile_raw + sw_byte(8 * c + j, node));
                float b = *reinterpret_cast<const float*>(
                              tile_raw + sw_byte(8 * c + j + 1, node));
                hh[j >> 1] = __floats2half2_rn(a, b);
            }
            uint4 val;
            __builtin_memcpy(&val, hh, 16);
            st_hint_v4(g_pk_raw + (size_t)k * (REC / 8) + c, val, pol);
        }
    }
}

// ---------------------------------------------------------------------------
// Kernel 2: gather + dot (R7-proven, byte-identical). 8 threads per query;
// thread j = head j. out layout: [pos: nq*8][neg: nq*8]
// ---------------------------------------------------------------------------
__global__ __launch_bounds__(256) void gather_dot_kernel(
    const float* __restrict__ q_phi,
    const int*   __restrict__ k_indices,
    float* __restrict__ out,
    int nq)
{
    int t = blockIdx.x * blockDim.x + threadIdx.x;
    int i = t >> 3;
    if (i >= nq) return;
    int h = t & 7;

    const uint64_t pol = mk_evict_last_policy();

    int k = __ldcs(k_indices + i);

    const float4* qp = reinterpret_cast<const float4*>(
        q_phi + (size_t)i * FEAT + h * MH_DIM);
    float4 q0 = __ldcs(qp);
    float4 q1 = __ldcs(qp + 1);

    const uint4* rec = g_pk_raw + (size_t)k * (REC / 8);
    uint4 pr = ld_hint_v4(rec + h, pol);
    uint4 nr = ld_hint_v4(rec + 8 + h, pol);

    const __half2* ph = reinterpret_cast<const __half2*>(&pr);
    const __half2* nh = reinterpret_cast<const __half2*>(&nr);

    float2 p0 = __half22float2(ph[0]);
    float2 p1 = __half22float2(ph[1]);
    float2 p2 = __half22float2(ph[2]);
    float2 p3 = __half22float2(ph[3]);
    float2 n0 = __half22float2(nh[0]);
    float2 n1 = __half22float2(nh[1]);
    float2 n2 = __half22float2(nh[2]);
    float2 n3 = __half22float2(nh[3]);

    float dp = q0.x * p0.x + q0.y * p0.y + q0.z * p1.x + q0.w * p1.y
             + q1.x * p2.x + q1.y * p2.y + q1.z * p3.x + q1.w * p3.y;
    float dn = q0.x * n0.x + q0.y * n0.y + q0.z * n1.x + q0.w * n1.y
             + q1.x * n2.x + q1.y * n2.y + q1.z * n3.x + q1.w * n3.y;

    __stcs(out + (size_t)i * H_DIM + h, dp);
    __stcs(out + (size_t)nq * H_DIM + (size_t)i * H_DIM + h, dn);
}

extern "C" void kernel_launch(void* const* d_in, const int* in_sizes, int n_in,
                              void* d_out, int out_size)
{
    const float* q_phi   = (const float*)d_in[0];
    const float* phi_pos = (const float*)d_in[1];
    const float* phi_neg = (const float*)d_in[2];
    const float* deg_pos = (const float*)d_in[3];
    const float* deg_neg = (const float*)d_in[4];
    const int*   k_idx   = (const int*)d_in[5];

    int nq      = in_sizes[5];                    // k_indices has N_Q elements
    int n_nodes = in_sizes[3] / H_DIM;            // deg_pos is [N][H]
    if (n_nodes > MAX_NODES) n_nodes = MAX_NODES;

    int tblocks = (n_nodes + TILE_N - 1) / TILE_N;
    transpose_fold_kernel<<<tblocks, 256>>>(phi_pos, phi_neg, deg_pos,
                                            deg_neg, n_nodes);

    int total   = nq * H_DIM;
    int gblocks = (total + 255) / 256;
    gather_dot_kernel<<<gblocks, 256>>>(q_phi, k_idx, (float*)d_out, nq);
}

// round 14
// speedup vs baseline: 2.3439x; 1.1584x over previous
#include <cuda_runtime.h>
#include <cuda_fp16.h>
#include <cstdint>

// Problem constants (fixed-shape problem: H=8, MH=8, N_NODES=500000)
#define H_DIM 8
#define MH_DIM 8
#define FEAT 64              // H*MH per sign
#define REC 128              // 2 signs * FEAT values per node record
#define MAX_NODES 500000
#define TILE_N 64            // nodes per transpose tile

// Node-major scratch in fp16: [node][sign][h][mh], 256B per node,
// deg-normalization folded in. uint4 type guarantees 16B alignment.
__device__ uint4 g_pk_raw[(size_t)MAX_NODES * REC / 8];

// ---- L2 eviction-priority helpers (cache_hint form) ----
__device__ __forceinline__ uint64_t mk_evict_last_policy() {
    uint64_t pol;
    asm("createpolicy.fractional.L2::evict_last.b64 %0, 1.0;" : "=l"(pol));
    return pol;
}
__device__ __forceinline__ void st_hint_v4(void* p, uint4 v, uint64_t pol) {
    asm volatile("st.global.L2::cache_hint.v4.b32 [%0], {%1,%2,%3,%4}, %5;"
                 :: "l"(p), "r"(v.x), "r"(v.y), "r"(v.z), "r"(v.w), "l"(pol));
}
__device__ __forceinline__ uint4 ld_hint_v4(const void* p, uint64_t pol) {
    uint4 r;
    asm volatile("ld.global.L2::cache_hint.v4.u32 {%0,%1,%2,%3}, [%4], %5;"
                 : "=r"(r.x), "=r"(r.y), "=r"(r.z), "=r"(r.w)
                 : "l"(p), "l"(pol));
    return r;
}

// Swizzled byte offset of (feat f, node n) in the 64x64 float tile
// (row = 256B). Conflict-free phase-1 stores, <=2-way phase-2 reads.
__device__ __forceinline__ int sw_byte(int f, int n) {
    int off = f * 256 + n * 4;
    int x = ((off >> 7) ^ (off >> 11)) & 7;
    return off ^ (x << 4);
}

// ---------------------------------------------------------------------------
// Kernel 1 (per sign): transpose [h][mh][N] -> scratch[k][sign][h][mh] fp16,
// folding 1/max(deg,1). Block: 256 threads, tile 64 nodes x 64 features.
// ONE SIGN per launch: each block touches only 64 phi pages (2MB pages at
// 2MB row stride) -> per-SM TLB working set ~64 entries instead of 128+.
// ---------------------------------------------------------------------------
__global__ __launch_bounds__(256) void transpose_fold_sign_kernel(
    const float* __restrict__ phi,     // [FEAT][N] for this sign
    const float* __restrict__ deg,     // [N][H]    for this sign
    int sgn8,                          // 0 (pos) or 8 (neg): chunk offset
    int n_nodes)
{
    __shared__ __align__(16) char tile_raw[64 * 256];    // 16KB
    __shared__ float inv[TILE_N][H_DIM];                 // 2KB

    const int k0 = blockIdx.x * TILE_N;
    const int t  = threadIdx.x;
    const uint64_t pol = mk_evict_last_policy();
    const bool full = (k0 + TILE_N <= n_nodes) && ((n_nodes & 3) == 0);

    // ---- inv table: 64 nodes * 8 heads = 512 values ----
    #pragma unroll
    for (int it = 0; it < 2; ++it) {
        int idx  = t + it * 256;            // node*8 + h
        int node = idx >> 3;
        int h    = idx & 7;
        int k    = k0 + node;
        float d  = 1.0f;
        if (k < n_nodes)
            d = __ldcs(deg + (size_t)k * H_DIM + h);
        inv[node][h] = 1.0f / fmaxf(d, 1.0f);
    }
    __syncthreads();

    // ---- phase 1: 64 feat-rows x 16 float4 groups (64 nodes) ----
    if (full) {
        #pragma unroll
        for (int it = 0; it < 4; ++it) {
            int l = t + it * 256;           // 0..1023
            int f = l >> 4;                 // feat row 0..63
            int g = l & 15;                 // float4 group (4 nodes)
            float4 v = __ldcs(reinterpret_cast<const float4*>(
                phi + (size_t)f * n_nodes + k0 + 4 * g));
            *reinterpret_cast<float4*>(tile_raw + sw_byte(f, 4 * g)) = v;
        }
    } else {
        #pragma unroll 4
        for (int it = 0; it < 16; ++it) {
            int l  = t + it * 256;          // 64*64 = 4096 elements
            int f  = l >> 6;
            int kk = l & 63;
            int k  = k0 + kk;
            float v = 0.0f;
            if (k < n_nodes)
                v = __ldcs(phi + (size_t)f * n_nodes + k);
            *reinterpret_cast<float*>(tile_raw + sw_byte(f, kk)) = v;
        }
    }
    __syncthreads();

    // ---- phase 2: 64 nodes x 8 chunks; chunk c = head c = feats 8c..8c+7 ----
    #pragma unroll
    for (int it = 0; it < 2; ++it) {
        int l    = t + it * 256;            // 0..511
        int node = l >> 3;
        int c    = l & 7;
        int k    = k0 + node;
        if (k < n_nodes) {
            float sc = inv[node][c];
            __half2 hh[4];
            #pragma unroll
            for (int j = 0; j < 8; j += 2) {
                float a = *reinterpret_cast<const float*>(
                              tile_raw + sw_byte(8 * c + j, node)) * sc;
                float b = *reinterpret_cast<const float*>(
                              tile_raw + sw_byte(8 * c + j + 1, node)) * sc;
                hh[j >> 1] = __floats2half2_rn(a, b);
            }
            uint4 val;
            __builtin_memcpy(&val, hh, 16);
            st_hint_v4(g_pk_raw + (size_t)k * (REC / 8) + sgn8 + c, val, pol);
        }
    }
}

// ---------------------------------------------------------------------------
// Kernel 2: gather + dot (champion, byte-identical). 8 threads per query;
// thread j = head j. out layout: [pos: nq*8][neg: nq*8]
// ---------------------------------------------------------------------------
__global__ __launch_bounds__(256) void gather_dot_kernel(
    const float* __restrict__ q_phi,
    const int*   __restrict__ k_indices,
    float* __restrict__ out,
    int nq)
{
    int t = blockIdx.x * blockDim.x + threadIdx.x;
    int i = t >> 3;
    if (i >= nq) return;
    int h = t & 7;

    const uint64_t pol = mk_evict_last_policy();

    int k = __ldcs(k_indices + i);

    const float4* qp = reinterpret_cast<const float4*>(
        q_phi + (size_t)i * FEAT + h * MH_DIM);
    float4 q0 = __ldcs(qp);
    float4 q1 = __ldcs(qp + 1);

    const uint4* rec = g_pk_raw + (size_t)k * (REC / 8);
    uint4 pr = ld_hint_v4(rec + h, pol);
    uint4 nr = ld_hint_v4(rec + 8 + h, pol);

    const __half2* ph = reinterpret_cast<const __half2*>(&pr);
    const __half2* nh = reinterpret_cast<const __half2*>(&nr);

    float2 p0 = __half22float2(ph[0]);
    float2 p1 = __half22float2(ph[1]);
    float2 p2 = __half22float2(ph[2]);
    float2 p3 = __half22float2(ph[3]);
    float2 n0 = __half22float2(nh[0]);
    float2 n1 = __half22float2(nh[1]);
    float2 n2 = __half22float2(nh[2]);
    float2 n3 = __half22float2(nh[3]);

    float dp = q0.x * p0.x + q0.y * p0.y + q0.z * p1.x + q0.w * p1.y
             + q1.x * p2.x + q1.y * p2.y + q1.z * p3.x + q1.w * p3.y;
    float dn = q0.x * n0.x + q0.y * n0.y + q0.z * n1.x + q0.w * n1.y
             + q1.x * n2.x + q1.y * n2.y + q1.z * n3.x + q1.w * n3.y;

    __stcs(out + (size_t)i * H_DIM + h, dp);
    __stcs(out + (size_t)nq * H_DIM + (size_t)i * H_DIM + h, dn);
}

extern "C" void kernel_launch(void* const* d_in, const int* in_sizes, int n_in,
                              void* d_out, int out_size)
{
    const float* q_phi   = (const float*)d_in[0];
    const float* phi_pos = (const float*)d_in[1];
    const float* phi_neg = (const float*)d_in[2];
    const float* deg_pos = (const float*)d_in[3];
    const float* deg_neg = (const float*)d_in[4];
    const int*   k_idx   = (const int*)d_in[5];

    int nq      = in_sizes[5];                    // k_indices has N_Q elements
    int n_nodes = in_sizes[3] / H_DIM;            // deg_pos is [N][H]
    if (n_nodes > MAX_NODES) n_nodes = MAX_NODES;

    int tblocks = (n_nodes + TILE_N - 1) / TILE_N;
    transpose_fold_sign_kernel<<<tblocks, 256>>>(phi_pos, deg_pos, 0, n_nodes);
    transpose_fold_sign_kernel<<<tblocks, 256>>>(phi_neg, deg_neg, 8, n_nodes);

    int total   = nq * H_DIM;
    int gblocks = (total + 255) / 256;
    gather_dot_kernel<<<gblocks, 256>>>(q_phi, k_idx, (float*)d_out, nq);
}